// round 1
// baseline (speedup 1.0000x reference)
#include <cuda_runtime.h>
#include <cstdint>
#include <cstddef>

// ---------------------------------------------------------------------------
// HoMESecondLayer: fused multi-task MoE second layer, fp32 SIMT baseline.
//
// Shapes: B=65536, META=128, GIN=256, H1=128, H2=64, EOUT=64, GH=64,
//         T1=64, T2=32, RANK=8, NTASK=4, NEXP_TASK=4, TASK_TO_GROUP={0,0,1,1}
//
// Grid: (B/32, 4 tasks). Each block: 32 rows, 256 threads, everything fused.
// ---------------------------------------------------------------------------

constexpr int ROWS    = 32;
constexpr int THREADS = 256;
constexpr int META    = 128;
constexpr int GIN     = 256;

// Padded pitches (floats) to keep float4 alignment + avoid bank conflicts.
constexpr int CMP = 260;   // cm buffer pitch (256 cols)
constexpr int AP  = 132;   // 128-col buffer pitch
constexpr int BP  = 68;    // 64-col buffer pitch

struct Smem {
    float cm [ROWS * CMP];   // gated concat(z_shared, z_group)
    float a  [ROWS * AP];    // h1 / tower h1
    float b  [ROWS * BP];    // h2 / task-gate hidden
    float c  [ROWS * BP];    // expert out e / tower h2
    float agg[ROWS * BP];    // expert aggregation
    float r  [ROWS * 8];     // low-rank gate intermediate
    float gw [ROWS * 4];     // softmax task-gate weights
    float lg [ROWS * 4];     // task-gate logits
};

__device__ __forceinline__ float sigm(float x)  { return 1.0f / (1.0f + __expf(-x)); }
__device__ __forceinline__ float swishf(float x){ return x   / (1.0f + __expf(-x)); }

// C[32][N] = act( A[32][K] @ W[K][N] + bias ), A in smem, W/bias in global.
// Thread layout: CT = N/4 column-threads, TM = N/32 rows per thread.
template<int N, int K, int APITCH, int CPITCH, bool SW>
__device__ __forceinline__ void gemm_tile(const float* As,
                                          const float* __restrict__ Wg,
                                          const float* __restrict__ bg,
                                          float* Cs, int tid)
{
    constexpr int TM = N / 32;
    constexpr int CT = N / 4;
    const int tc  = tid % CT;
    const int tr  = tid / CT;
    const int col = tc * 4;

    float acc[TM][4];
#pragma unroll
    for (int m = 0; m < TM; m++) {
        acc[m][0] = 0.f; acc[m][1] = 0.f; acc[m][2] = 0.f; acc[m][3] = 0.f;
    }

    for (int k = 0; k < K; k += 4) {
        float4 av[TM];
#pragma unroll
        for (int m = 0; m < TM; m++)
            av[m] = *reinterpret_cast<const float4*>(As + (tr * TM + m) * APITCH + k);
#pragma unroll
        for (int kk = 0; kk < 4; kk++) {
            const float4 w = __ldg(reinterpret_cast<const float4*>(
                Wg + (size_t)(k + kk) * N + col));
#pragma unroll
            for (int m = 0; m < TM; m++) {
                const float a = (kk == 0) ? av[m].x :
                                (kk == 1) ? av[m].y :
                                (kk == 2) ? av[m].z : av[m].w;
                acc[m][0] = fmaf(a, w.x, acc[m][0]);
                acc[m][1] = fmaf(a, w.y, acc[m][1]);
                acc[m][2] = fmaf(a, w.z, acc[m][2]);
                acc[m][3] = fmaf(a, w.w, acc[m][3]);
            }
        }
    }

    const float4 bv = __ldg(reinterpret_cast<const float4*>(bg + col));
#pragma unroll
    for (int m = 0; m < TM; m++) {
        float r0 = acc[m][0] + bv.x;
        float r1 = acc[m][1] + bv.y;
        float r2 = acc[m][2] + bv.z;
        float r3 = acc[m][3] + bv.w;
        if (SW) { r0 = swishf(r0); r1 = swishf(r1); r2 = swishf(r2); r3 = swishf(r3); }
        float* cp = Cs + (tr * TM + m) * CPITCH + col;
        cp[0] = r0; cp[1] = r1; cp[2] = r2; cp[3] = r3;
    }
}

__global__ __launch_bounds__(THREADS, 2)
void home_kernel(
    const float* __restrict__ z_shared, const float* __restrict__ z_g0,
    const float* __restrict__ z_g1,
    const float* __restrict__ exp_W1, const float* __restrict__ exp_b1,
    const float* __restrict__ exp_W2, const float* __restrict__ exp_b2,
    const float* __restrict__ exp_W3, const float* __restrict__ exp_b3,
    const float* __restrict__ ln_s,   const float* __restrict__ ln_b,
    const float* __restrict__ fg_A,   const float* __restrict__ fg_B,
    const float* __restrict__ tg_W1,  const float* __restrict__ tg_b1,
    const float* __restrict__ tg_W2,  const float* __restrict__ tg_b2,
    const float* __restrict__ sg_W,   const float* __restrict__ sg_b,
    const float* __restrict__ tw_W1,  const float* __restrict__ tw_b1,
    const float* __restrict__ tw_W2,  const float* __restrict__ tw_b2,
    const float* __restrict__ tw_W3,  const float* __restrict__ tw_b3,
    float* __restrict__ out)
{
    extern __shared__ char smem_raw[];
    Smem& s = *reinterpret_cast<Smem*>(smem_raw);

    const int tid  = threadIdx.x;
    const int t    = blockIdx.y;          // task
    const int row0 = blockIdx.x * ROWS;
    const int g    = t >> 1;              // TASK_TO_GROUP = {0,0,1,1}
    const float* zg = g ? z_g1 : z_g0;

    // ---- 1. Load cm = concat(z_shared, z_group[g]) into smem -------------
    for (int idx = tid; idx < ROWS * GIN / 4; idx += THREADS) {
        const int row = idx >> 6;       // 64 float4 per row
        const int k   = (idx & 63) * 4;
        float4 v;
        if (k < META)
            v = *reinterpret_cast<const float4*>(z_shared + (size_t)(row0 + row) * META + k);
        else
            v = *reinterpret_cast<const float4*>(zg + (size_t)(row0 + row) * META + (k - META));
        *reinterpret_cast<float4*>(&s.cm[row * CMP + k]) = v;
    }
    __syncthreads();

    // ---- 2a. r = cm @ fg_A[t]  (32 x 8) ----------------------------------
    {
        const int row = tid >> 3, j = tid & 7;
        const float* A   = fg_A + (size_t)t * GIN * 8;
        const float* cmr = &s.cm[row * CMP];
        float acc = 0.f;
#pragma unroll 4
        for (int k = 0; k < GIN; k++)
            acc = fmaf(cmr[k], __ldg(&A[k * 8 + j]), acc);
        s.r[row * 8 + j] = acc;
    }
    __syncthreads();

    // ---- 2b. cm *= 2*sigmoid(r @ fg_B[t]) --------------------------------
    {
        const float* Bm = fg_B + (size_t)t * 8 * GIN;
        for (int idx = tid; idx < ROWS * GIN; idx += THREADS) {
            const int row = idx >> 8, k = idx & 255;
            const float* rr = &s.r[row * 8];
            float acc = 0.f;
#pragma unroll
            for (int j = 0; j < 8; j++)
                acc = fmaf(rr[j], __ldg(&Bm[j * GIN + k]), acc);
            s.cm[row * CMP + k] *= 2.0f * sigm(acc);
        }
    }
    __syncthreads();

    // ---- 3. Task gate: gh = swish(cm @ tg_W1 + b), gw = softmax(...) -----
    gemm_tile<64, 256, CMP, BP, true>(s.cm, tg_W1 + (size_t)t * GIN * 64,
                                      tg_b1 + t * 64, s.b, tid);
    __syncthreads();
    if (tid < 128) {
        const int row = tid >> 2, j = tid & 3;
        const float* W  = tg_W2 + (size_t)t * 64 * 4;
        const float* gh = &s.b[row * BP];
        float acc = __ldg(&tg_b2[t * 4 + j]);
#pragma unroll 4
        for (int c = 0; c < 64; c++)
            acc = fmaf(gh[c], __ldg(&W[c * 4 + j]), acc);
        s.lg[row * 4 + j] = acc;
    }
    __syncthreads();
    if (tid < 32) {
        const float l0 = s.lg[tid * 4 + 0], l1 = s.lg[tid * 4 + 1];
        const float l2 = s.lg[tid * 4 + 2], l3 = s.lg[tid * 4 + 3];
        const float m  = fmaxf(fmaxf(l0, l1), fmaxf(l2, l3));
        const float e0 = __expf(l0 - m), e1 = __expf(l1 - m);
        const float e2 = __expf(l2 - m), e3 = __expf(l3 - m);
        const float inv = 1.0f / (e0 + e1 + e2 + e3);
        s.gw[tid * 4 + 0] = e0 * inv; s.gw[tid * 4 + 1] = e1 * inv;
        s.gw[tid * 4 + 2] = e2 * inv; s.gw[tid * 4 + 3] = e3 * inv;
    }
    __syncthreads();

    // ---- 4. Expert loop: eidx = {0, 1, 2+2g, 3+2g} ------------------------
    const int wid = tid >> 5, lane = tid & 31;
#pragma unroll 1
    for (int ep = 0; ep < 4; ep++) {
        const int e = (ep < 2) ? ep : (ep + 2 * g);

        gemm_tile<128, 256, CMP, AP, true >(s.cm, exp_W1 + (size_t)e * GIN * 128,
                                            exp_b1 + e * 128, s.a, tid);
        __syncthreads();
        gemm_tile<64, 128, AP, BP, true >(s.a,  exp_W2 + (size_t)e * 128 * 64,
                                          exp_b2 + e * 64, s.b, tid);
        __syncthreads();
        gemm_tile<64, 64,  BP, BP, false>(s.b,  exp_W3 + (size_t)e * 64 * 64,
                                          exp_b3 + e * 64, s.c, tid);
        __syncthreads();

        // LayerNorm + diag self-gate + weighted aggregation (warp per 4 rows)
        {
            const float* lS  = ln_s + e * 64;
            const float* lB  = ln_b + e * 64;
            const float* sgw = sg_W + (size_t)t * 64 * 4;
            const float  sgb = __ldg(&sg_b[t * 4 + ep]);
#pragma unroll
            for (int rr = 0; rr < 4; rr++) {
                const int row = wid * 4 + rr;
                const float v0 = s.c[row * BP + lane];
                const float v1 = s.c[row * BP + lane + 32];
                float sum = v0 + v1;
                float sq  = fmaf(v0, v0, v1 * v1);
#pragma unroll
                for (int o = 16; o; o >>= 1) {
                    sum += __shfl_xor_sync(0xffffffffu, sum, o);
                    sq  += __shfl_xor_sync(0xffffffffu, sq,  o);
                }
                const float mu  = sum * (1.0f / 64.0f);
                const float var = sq * (1.0f / 64.0f) - mu * mu;
                const float inv = rsqrtf(var + 1e-5f);
                const float n0  = fmaf((v0 - mu) * inv, __ldg(&lS[lane]),      __ldg(&lB[lane]));
                const float n1  = fmaf((v1 - mu) * inv, __ldg(&lS[lane + 32]), __ldg(&lB[lane + 32]));
                float swp = fmaf(n0, __ldg(&sgw[lane * 4 + ep]),
                                 n1 * __ldg(&sgw[(lane + 32) * 4 + ep]));
#pragma unroll
                for (int o = 16; o; o >>= 1)
                    swp += __shfl_xor_sync(0xffffffffu, swp, o);
                const float scale = (swp + sgb) * s.gw[row * 4 + ep];
                if (ep == 0) {
                    s.agg[row * BP + lane]      = n0 * scale;
                    s.agg[row * BP + lane + 32] = n1 * scale;
                } else {
                    s.agg[row * BP + lane]      += n0 * scale;
                    s.agg[row * BP + lane + 32] += n1 * scale;
                }
            }
        }
        __syncthreads();
    }

    // ---- 5. Tower: agg -> 64 -> 32 -> 1 -----------------------------------
    gemm_tile<64, 64, BP, AP, true>(s.agg, tw_W1 + (size_t)t * 64 * 64,
                                    tw_b1 + t * 64, s.a, tid);
    __syncthreads();
    gemm_tile<32, 64, AP, BP, true>(s.a, tw_W2 + (size_t)t * 64 * 32,
                                    tw_b2 + t * 32, s.c, tid);
    __syncthreads();
    if (tid < 32) {
        const float* th = &s.c[tid * BP];
        const float* W  = tw_W3 + t * 32;
        float acc = __ldg(&tw_b3[t]);
#pragma unroll 4
        for (int c = 0; c < 32; c++)
            acc = fmaf(th[c], __ldg(&W[c]), acc);
        out[(size_t)(row0 + tid) * 4 + t] = sigm(acc);
    }
}

extern "C" void kernel_launch(void* const* d_in, const int* in_sizes, int n_in,
                              void* d_out, int out_size)
{
    (void)n_in; (void)out_size;
    const float* zs   = (const float*)d_in[0];
    const float* z0   = (const float*)d_in[1];
    const float* z1   = (const float*)d_in[2];
    // d_in[3] = v (unused by the reference computation)
    const float* eW1  = (const float*)d_in[4];
    const float* eb1  = (const float*)d_in[5];
    const float* eW2  = (const float*)d_in[6];
    const float* eb2  = (const float*)d_in[7];
    const float* eW3  = (const float*)d_in[8];
    const float* eb3  = (const float*)d_in[9];
    const float* lns  = (const float*)d_in[10];
    const float* lnb  = (const float*)d_in[11];
    const float* fgA  = (const float*)d_in[12];
    const float* fgB  = (const float*)d_in[13];
    const float* tgW1 = (const float*)d_in[14];
    const float* tgb1 = (const float*)d_in[15];
    const float* tgW2 = (const float*)d_in[16];
    const float* tgb2 = (const float*)d_in[17];
    const float* sgW  = (const float*)d_in[18];
    const float* sgb  = (const float*)d_in[19];
    const float* twW1 = (const float*)d_in[20];
    const float* twb1 = (const float*)d_in[21];
    const float* twW2 = (const float*)d_in[22];
    const float* twb2 = (const float*)d_in[23];
    const float* twW3 = (const float*)d_in[24];
    const float* twb3 = (const float*)d_in[25];

    const int Bn = in_sizes[0] / META;

    cudaFuncSetAttribute(home_kernel, cudaFuncAttributeMaxDynamicSharedMemorySize,
                         (int)sizeof(Smem));

    dim3 grid(Bn / ROWS, 4);
    home_kernel<<<grid, THREADS, sizeof(Smem)>>>(
        zs, z0, z1, eW1, eb1, eW2, eb2, eW3, eb3, lns, lnb,
        fgA, fgB, tgW1, tgb1, tgW2, tgb2, sgW, sgb,
        twW1, twb1, twW2, twb2, twW3, twb3, (float*)d_out);
}